// round 15
// baseline (speedup 1.0000x reference)
#include <cuda_runtime.h>
#include <cuda_bf16.h>
#include <stdint.h>
#include <math.h>

// ---------------- problem constants ----------------
#define N_NODES   500000
#define HIDDEN    256
#define NCLASS    104
#define AUXD      2
#define NGRAPH    2048
#define GRAPHX    128
#define DIN       (NCLASS + AUXD)
#define BN_EPS    1e-5f

// ---------------- main-kernel tiling ----------------
#define BM        128               // nodes per block
#define TB        384               // 12 warps: 4 m-groups x 3 n-groups
#define NT        13                // 13 n8 tiles = 104 classes
#define KC        16                // K per chunk (2 k8 steps)
#define NCHUNK    (HIDDEN / KC)     // 16
#define AST       20                // A smem row stride (floats)

// SMEM float offsets
#define A_FLTS    (BM * AST)                    // 2560 per array
#define OFF_A(buf, which) (((buf) * 2 + (which)) * A_FLTS)
#define B_CHUNK_U32 (3 * 2 * NT * 32 * 2)       // 4992 uint32 per chunk
#define OFF_B(buf)  (4 * A_FLTS + (buf) * B_CHUNK_U32)
#define SMEM_MAIN   ((4 * A_FLTS + 2 * B_CHUNK_U32) * 4)   // 80896 B
#define SMEM_BYTES  (SMEM_MAIN + 512)

// ---------------- device scratch ----------------
__device__ float g_pool[NGRAPH * NCLASS];
// tf32 weights packed in b-fragment order: [chunk][mat(3)][s(2)][j(13)][lane(32)][2]
__device__ uint32_t g_wb[NCHUNK][B_CHUNK_U32];

// ---------------- helpers ----------------
__device__ __forceinline__ float sigmoidf_(float x) {
    return 1.0f / (1.0f + expf(-x));
}
__device__ __forceinline__ void cp16(uint32_t dst, const void* src, int srcsz) {
    asm volatile("cp.async.cg.shared.global [%0], [%1], 16, %2;"
                 :: "r"(dst), "l"(src), "r"(srcsz));
}
__device__ __forceinline__ void cp16f(uint32_t dst, const void* src) {
    asm volatile("cp.async.cg.shared.global [%0], [%1], 16;"
                 :: "r"(dst), "l"(src));
}
__device__ __forceinline__ uint32_t f2tf(float x) {
    uint32_t u;
    asm("cvt.rna.tf32.f32 %0, %1;" : "=r"(u) : "f"(x));
    return u;
}
__device__ __forceinline__ void mma_tf32(float* d, const uint32_t* a, uint2 b) {
    asm volatile(
        "mma.sync.aligned.m16n8k8.row.col.f32.tf32.tf32.f32 "
        "{%0,%1,%2,%3}, {%4,%5,%6,%7}, {%8,%9}, {%0,%1,%2,%3};"
        : "+f"(d[0]), "+f"(d[1]), "+f"(d[2]), "+f"(d[3])
        : "r"(a[0]), "r"(a[1]), "r"(a[2]), "r"(a[3]), "r"(b.x), "r"(b.y));
}

// ---------------- fused prep: zero pool + pack tf32 b-fragments ----------------
__global__ void prep_kernel(const float* __restrict__ Wg,
                            const float* __restrict__ Wt) {
    int idx = blockIdx.x * blockDim.x + threadIdx.x;
    if (idx < NGRAPH * NCLASS) g_pool[idx] = 0.0f;
    if (idx < NCHUNK * B_CHUNK_U32) {
        int e = idx;
        int p = e & 1;  e >>= 1;
        int t = e & 31; e >>= 5;
        int j = e % NT; e /= NT;
        int s = e & 1;  e >>= 1;
        int mat = e % 3; e /= 3;
        int c = e;                                   // chunk
        int k = c * KC + s * 8 + (t & 3) + p * 4;    // 0..255
        int n = j * 8 + (t >> 2);                    // 0..103
        float v;
        if (mat == 0)      v = Wg[(size_t)k * NCLASS + n];
        else if (mat == 1) v = Wg[(size_t)(HIDDEN + k) * NCLASS + n];
        else               v = Wt[(size_t)k * NCLASS + n];
        g_wb[c][(((mat * 2 + s) * NT + j) * 32 + t) * 2 + p] = f2tf(v);
    }
}

// ---------------- Kernel A: HMMA gated readout + segment pooling ----------------
__global__ __launch_bounds__(TB, 1)
void nodewise_kernel(const float* __restrict__ init_states,
                     const float* __restrict__ fin_states,
                     const int*   __restrict__ gids,
                     const float* __restrict__ bg,
                     const float* __restrict__ bt)
{
    extern __shared__ float sm[];
    uint32_t* smB = (uint32_t*)sm;
    int* sg = (int*)((char*)sm + SMEM_MAIN);    // [BM]
    const uint32_t smem_u32 = (uint32_t)__cvta_generic_to_shared(sm);

    const int tid  = threadIdx.x;
    const int w    = tid / 32;
    const int lane = tid % 32;
    const int wm   = w & 3;             // m-group: SMSP id -> balanced
    const int wn   = w >> 2;            // n-group 0..2
    const int jbase = (wn == 0) ? 0 : (5 + (wn - 1) * 4);
    const int jcnt  = (wn == 0) ? 5 : 4;
    const int n0   = blockIdx.x * BM;

    for (int i = tid; i < BM; i += TB) {
        int n = n0 + i;
        sg[i] = (n < N_NODES) ? gids[n] : -1;
    }

    // ---- async staging of one chunk ----
    auto stage = [&](int c) {
        const int buf = c & 1;
        // A: 1024 float4 tasks (init+fin, 128 rows x 4 quarters)
        for (int task = tid; task < 1024; task += TB) {
            int which = task >> 9;
            int rem   = task & 511;
            int m     = rem >> 2;
            int kq    = rem & 3;
            int n     = n0 + m;
            int nc    = (n < N_NODES) ? n : 0;
            const float* src = (which ? fin_states : init_states)
                               + (size_t)nc * HIDDEN + c * KC + kq * 4;
            uint32_t dst = smem_u32 + (OFF_A(buf, which) + m * AST + kq * 4) * 4;
            cp16(dst, src, (n < N_NODES) ? 16 : 0);
        }
        // B: 1248 float4 (pre-packed fragments, verbatim)
        for (int u = tid; u < B_CHUNK_U32 / 4; u += TB) {
            cp16f(smem_u32 + (OFF_B(buf) + u * 4) * 4, &g_wb[c][u * 4]);
        }
        asm volatile("cp.async.commit_group;");
    };

    float ga[2][5][4], ta[2][5][4];
    #pragma unroll
    for (int mt = 0; mt < 2; mt++)
        #pragma unroll
        for (int j = 0; j < 5; j++)
            #pragma unroll
            for (int q = 0; q < 4; q++) { ga[mt][j][q] = 0.0f; ta[mt][j][q] = 0.0f; }

    stage(0);
    stage(1);

    const int g  = lane >> 2;
    const int t4 = lane & 3;

    for (int c = 0; c < NCHUNK; c++) {
        if (c >= NCHUNK - 2) asm volatile("cp.async.wait_group 0;");
        else                 asm volatile("cp.async.wait_group 1;");
        __syncthreads();

        const int buf = c & 1;
        const float* Ai = sm + OFF_A(buf, 0);
        const float* Af = sm + OFF_A(buf, 1);
        const uint2* Bp = (const uint2*)(smB + OFF_B(buf));

        #pragma unroll
        for (int s = 0; s < 2; s++) {
            const int col = s * 8 + t4;
            uint32_t ai[2][4], af[2][4];
            #pragma unroll
            for (int mt = 0; mt < 2; mt++) {
                const int row = wm * 32 + mt * 16 + g;
                ai[mt][0] = f2tf(Ai[(row)     * AST + col]);
                ai[mt][1] = f2tf(Ai[(row + 8) * AST + col]);
                ai[mt][2] = f2tf(Ai[(row)     * AST + col + 4]);
                ai[mt][3] = f2tf(Ai[(row + 8) * AST + col + 4]);
                af[mt][0] = f2tf(Af[(row)     * AST + col]);
                af[mt][1] = f2tf(Af[(row + 8) * AST + col]);
                af[mt][2] = f2tf(Af[(row)     * AST + col + 4]);
                af[mt][3] = f2tf(Af[(row + 8) * AST + col + 4]);
            }
            #pragma unroll 5
            for (int jj = 0; jj < jcnt; jj++) {
                const int j = jbase + jj;
                uint2 bgi = Bp[((0 + s) * NT + j) * 32 + lane];
                uint2 bgf = Bp[((2 + s) * NT + j) * 32 + lane];
                uint2 btt = Bp[((4 + s) * NT + j) * 32 + lane];
                #pragma unroll
                for (int mt = 0; mt < 2; mt++) {
                    mma_tf32(ga[mt][jj], ai[mt], bgi);
                    mma_tf32(ga[mt][jj], af[mt], bgf);
                    mma_tf32(ta[mt][jj], af[mt], btt);
                }
            }
        }
        __syncthreads();
        if (c + 2 < NCHUNK) stage(c + 2);
    }
    __syncthreads();    // all warps done reading smem before Gs overwrite

    // ---- epilogue: nodewise = sigmoid(gate + bg) * (t + bt) -> Gs ----
    float* Gs = sm;     // [BM][NCLASS], aliases staging buffers
    #pragma unroll 5
    for (int jj = 0; jj < jcnt; jj++) {
        const int j  = jbase + jj;
        const int c0 = j * 8 + 2 * t4;
        const float bg0 = __ldg(&bg[c0]), bg1 = __ldg(&bg[c0 + 1]);
        const float bt0 = __ldg(&bt[c0]), bt1 = __ldg(&bt[c0 + 1]);
        #pragma unroll
        for (int mt = 0; mt < 2; mt++) {
            #pragma unroll
            for (int h = 0; h < 2; h++) {
                int row = wm * 32 + mt * 16 + g + h * 8;
                float gv0 = ga[mt][jj][2 * h]     + bg0;
                float gv1 = ga[mt][jj][2 * h + 1] + bg1;
                float tv0 = ta[mt][jj][2 * h]     + bt0;
                float tv1 = ta[mt][jj][2 * h + 1] + bt1;
                Gs[row * NCLASS + c0]     = sigmoidf_(gv0) * tv0;
                Gs[row * NCLASS + c0 + 1] = sigmoidf_(gv1) * tv1;
            }
        }
    }
    __syncthreads();

    // ---- segmented pooling (nodes sorted by graph id) ----
    if (tid < 2 * NCLASS) {
        const int cc  = tid % NCLASS;
        const int seg = tid / NCLASS;
        int r   = seg * 64;
        int cur = sg[r];
        float s = 0.0f;
        #pragma unroll 4
        for (int i = 0; i < 64; i++, r++) {
            int gg = sg[r];
            if (gg != cur) {
                if (cur >= 0) atomicAdd(&g_pool[cur * NCLASS + cc], s);
                s = 0.0f;
                cur = gg;
            }
            if (gg >= 0) s += Gs[r * NCLASS + cc];
        }
        if (cur >= 0) atomicAdd(&g_pool[cur * NCLASS + cc], s);
    }
}

// ---------------- Kernel B: batched per-graph BN + MLP (8 graphs/block) ----------------
#define BG 8
__global__ __launch_bounds__(256)
void graph_mlp_kernel(const float* __restrict__ aux,
                      const float* __restrict__ bn_gamma, const float* __restrict__ bn_beta,
                      const float* __restrict__ bn_mean,  const float* __restrict__ bn_var,
                      const float* __restrict__ W1, const float* __restrict__ b1,
                      const float* __restrict__ W2, const float* __restrict__ b2,
                      float* __restrict__ out)
{
    __shared__ float norm[BG][DIN];
    __shared__ float h[BG][GRAPHX];
    const int g0  = blockIdx.x * BG;
    const int tid = threadIdx.x;

    for (int i = tid; i < BG * DIN; i += 256) {
        int gi = i / DIN, d = i % DIN;
        int g  = g0 + gi;
        float ext = (d < NCLASS) ? g_pool[g * NCLASS + d]
                                 : aux[g * AUXD + (d - NCLASS)];
        norm[gi][d] = (ext - bn_mean[d]) * rsqrtf(bn_var[d] + BN_EPS) * bn_gamma[d]
                      + bn_beta[d];
    }
    __syncthreads();

    // hidden: BG x (106 -> 128)
    for (int i = tid; i < BG * GRAPHX; i += 256) {
        int gi = i >> 7, hu = i & 127;
        float acc = b1[hu];
        #pragma unroll 2
        for (int d = 0; d < DIN; d++)
            acc = fmaf(norm[gi][d], __ldg(&W1[d * GRAPHX + hu]), acc);
        h[gi][hu] = fmaxf(acc, 0.0f);
    }
    __syncthreads();

    // logits: BG x (128 -> 104)
    for (int i = tid; i < BG * NCLASS; i += 256) {
        int gi = i / NCLASS, c = i % NCLASS;
        float acc = b2[c];
        #pragma unroll 4
        for (int j = 0; j < GRAPHX; j++)
            acc = fmaf(h[gi][j], __ldg(&W2[j * NCLASS + c]), acc);
        out[(g0 + gi) * NCLASS + c] = acc;
    }
}

// ---------------- launch ----------------
extern "C" void kernel_launch(void* const* d_in, const int* in_sizes, int n_in,
                              void* d_out, int out_size)
{
    const float* init_states = (const float*)d_in[0];
    const float* fin_states  = (const float*)d_in[1];
    const float* aux         = (const float*)d_in[2];
    const int*   gids        = (const int*)  d_in[3];
    // d_in[4] = num_graphs (compile-time constant)
    const float* Wg = (const float*)d_in[5];
    const float* bg = (const float*)d_in[6];
    const float* Wt = (const float*)d_in[7];
    const float* bt = (const float*)d_in[8];
    const float* bn_gamma = (const float*)d_in[9];
    const float* bn_beta  = (const float*)d_in[10];
    const float* bn_mean  = (const float*)d_in[11];
    const float* bn_var   = (const float*)d_in[12];
    const float* W1 = (const float*)d_in[13];
    const float* b1 = (const float*)d_in[14];
    const float* W2 = (const float*)d_in[15];
    const float* b2 = (const float*)d_in[16];
    float* out = (float*)d_out;

    // Unconditional; idempotent and capture-safe.
    cudaFuncSetAttribute(nodewise_kernel,
                         cudaFuncAttributeMaxDynamicSharedMemorySize, SMEM_BYTES);

    {
        int total = NGRAPH * NCLASS;     // >= NCHUNK * B_CHUNK_U32
        prep_kernel<<<(total + 255) / 256, 256>>>(Wg, Wt);
    }
    {
        int nblk = (N_NODES + BM - 1) / BM;
        nodewise_kernel<<<nblk, TB, SMEM_BYTES>>>(init_states, fin_states, gids, bg, bt);
    }
    graph_mlp_kernel<<<NGRAPH / BG, 256>>>(aux, bn_gamma, bn_beta, bn_mean, bn_var,
                                           W1, b1, W2, b2, out);
}

// round 17
// speedup vs baseline: 3.1234x; 3.1234x over previous
#include <cuda_runtime.h>
#include <cuda_bf16.h>
#include <stdint.h>
#include <math.h>

// ---------------- problem constants ----------------
#define N_NODES   500000
#define HIDDEN    256
#define NCLASS    104
#define AUXD      2
#define NGRAPH    2048
#define GRAPHX    128
#define DIN       (NCLASS + AUXD)
#define BN_EPS    1e-5f

// ---------------- main-kernel tiling ----------------
#define BM        128               // nodes per block
#define TB        384               // 12 warps: 4 m-groups x 3 n-groups
#define NT        13                // 13 n8 tiles = 104 classes
#define KC        16                // K per chunk (2 k8 steps)
#define NCHUNK    (HIDDEN / KC)     // 16
#define AST       20                // A smem row stride (floats)

// SMEM float offsets
#define A_FLTS    (BM * AST)                    // 2560 per array
#define OFF_A(buf, which) (((buf) * 2 + (which)) * A_FLTS)
#define B_CHUNK_U32 (3 * 2 * NT * 32 * 2)       // 4992 uint32 per chunk
#define OFF_B(buf)  (4 * A_FLTS + (buf) * B_CHUNK_U32)
#define SMEM_MAIN   ((4 * A_FLTS + 2 * B_CHUNK_U32) * 4)   // 80896 B
#define SMEM_BYTES  (SMEM_MAIN + 512)

// ---------------- device scratch ----------------
__device__ float g_pool[NGRAPH * NCLASS];
// tf32 weights packed in b-fragment order: [chunk][mat(3)][s(2)][j(13)][lane(32)][2]
__device__ uint32_t g_wb[NCHUNK][B_CHUNK_U32];

// ---------------- helpers ----------------
__device__ __forceinline__ float sigmoidf_(float x) {
    return 1.0f / (1.0f + expf(-x));
}
__device__ __forceinline__ void cp16(uint32_t dst, const void* src, int srcsz) {
    asm volatile("cp.async.cg.shared.global [%0], [%1], 16, %2;"
                 :: "r"(dst), "l"(src), "r"(srcsz));
}
__device__ __forceinline__ void cp16f(uint32_t dst, const void* src) {
    asm volatile("cp.async.cg.shared.global [%0], [%1], 16;"
                 :: "r"(dst), "l"(src));
}
__device__ __forceinline__ uint32_t f2tf(float x) {
    uint32_t u;
    asm("cvt.rna.tf32.f32 %0, %1;" : "=r"(u) : "f"(x));
    return u;
}
__device__ __forceinline__ void mma_tf32(float* d, const uint32_t* a, uint2 b) {
    asm volatile(
        "mma.sync.aligned.m16n8k8.row.col.f32.tf32.tf32.f32 "
        "{%0,%1,%2,%3}, {%4,%5,%6,%7}, {%8,%9}, {%0,%1,%2,%3};"
        : "+f"(d[0]), "+f"(d[1]), "+f"(d[2]), "+f"(d[3])
        : "r"(a[0]), "r"(a[1]), "r"(a[2]), "r"(a[3]), "r"(b.x), "r"(b.y));
}

// ---------------- fused prep: zero pool + pack tf32 b-fragments ----------------
__global__ void prep_kernel(const float* __restrict__ Wg,
                            const float* __restrict__ Wt) {
    int idx = blockIdx.x * blockDim.x + threadIdx.x;
    if (idx < NGRAPH * NCLASS) g_pool[idx] = 0.0f;
    if (idx < NCHUNK * B_CHUNK_U32) {
        int e = idx;
        int p = e & 1;  e >>= 1;
        int t = e & 31; e >>= 5;
        int j = e % NT; e /= NT;
        int s = e & 1;  e >>= 1;
        int mat = e % 3; e /= 3;
        int c = e;                                   // chunk
        int k = c * KC + s * 8 + (t & 3) + p * 4;    // 0..255
        int n = j * 8 + (t >> 2);                    // 0..103
        float v;
        if (mat == 0)      v = Wg[(size_t)k * NCLASS + n];
        else if (mat == 1) v = Wg[(size_t)(HIDDEN + k) * NCLASS + n];
        else               v = Wt[(size_t)k * NCLASS + n];
        g_wb[c][(((mat * 2 + s) * NT + j) * 32 + t) * 2 + p] = f2tf(v);
    }
}

// ---------------- templated mainloop: compile-time j-range per n-group ----------------
template<int JB, int JC>
__device__ __forceinline__ void run_path(const float* __restrict__ init_states,
                                         const float* __restrict__ fin_states,
                                         const float* __restrict__ bg,
                                         const float* __restrict__ bt,
                                         float* sm, uint32_t smem_u32,
                                         int n0, int tid, int wm, int lane)
{
    uint32_t* smB = (uint32_t*)sm;

    auto stage = [&](int c) {
        const int buf = c & 1;
        // A: 1024 float4 tasks (init+fin, 128 rows x 4 quarters)
        for (int task = tid; task < 1024; task += TB) {
            int which = task >> 9;
            int rem   = task & 511;
            int m     = rem >> 2;
            int kq    = rem & 3;
            int n     = n0 + m;
            int nc    = (n < N_NODES) ? n : 0;
            const float* src = (which ? fin_states : init_states)
                               + (size_t)nc * HIDDEN + c * KC + kq * 4;
            uint32_t dst = smem_u32 + (OFF_A(buf, which) + m * AST + kq * 4) * 4;
            cp16(dst, src, (n < N_NODES) ? 16 : 0);
        }
        // B: pre-packed fragments, verbatim
        for (int u = tid; u < B_CHUNK_U32 / 4; u += TB) {
            cp16f(smem_u32 + (OFF_B(buf) + u * 4) * 4, &g_wb[c][u * 4]);
        }
        asm volatile("cp.async.commit_group;");
    };

    float ga[2][JC][4], ta[2][JC][4];
    #pragma unroll
    for (int mt = 0; mt < 2; mt++)
        #pragma unroll
        for (int j = 0; j < JC; j++)
            #pragma unroll
            for (int q = 0; q < 4; q++) { ga[mt][j][q] = 0.0f; ta[mt][j][q] = 0.0f; }

    stage(0);
    stage(1);

    const int g  = lane >> 2;
    const int t4 = lane & 3;

    for (int c = 0; c < NCHUNK; c++) {
        if (c >= NCHUNK - 2) asm volatile("cp.async.wait_group 0;");
        else                 asm volatile("cp.async.wait_group 1;");
        __syncthreads();

        const int buf = c & 1;
        const float* Ai = sm + OFF_A(buf, 0);
        const float* Af = sm + OFF_A(buf, 1);
        const uint2* Bp = (const uint2*)(smB + OFF_B(buf));

        #pragma unroll
        for (int s = 0; s < 2; s++) {
            const int col = s * 8 + t4;
            uint32_t ai[2][4], af[2][4];
            #pragma unroll
            for (int mt = 0; mt < 2; mt++) {
                const int row = wm * 32 + mt * 16 + g;
                ai[mt][0] = f2tf(Ai[(row)     * AST + col]);
                ai[mt][1] = f2tf(Ai[(row + 8) * AST + col]);
                ai[mt][2] = f2tf(Ai[(row)     * AST + col + 4]);
                ai[mt][3] = f2tf(Ai[(row + 8) * AST + col + 4]);
                af[mt][0] = f2tf(Af[(row)     * AST + col]);
                af[mt][1] = f2tf(Af[(row + 8) * AST + col]);
                af[mt][2] = f2tf(Af[(row)     * AST + col + 4]);
                af[mt][3] = f2tf(Af[(row + 8) * AST + col + 4]);
            }
            #pragma unroll
            for (int jj = 0; jj < JC; jj++) {
                const int j = JB + jj;
                uint2 bgi = Bp[((0 + s) * NT + j) * 32 + lane];
                uint2 bgf = Bp[((2 + s) * NT + j) * 32 + lane];
                uint2 btt = Bp[((4 + s) * NT + j) * 32 + lane];
                #pragma unroll
                for (int mt = 0; mt < 2; mt++) {
                    mma_tf32(ga[mt][jj], ai[mt], bgi);
                    mma_tf32(ga[mt][jj], af[mt], bgf);
                    mma_tf32(ta[mt][jj], af[mt], btt);
                }
            }
        }
        __syncthreads();
        if (c + 2 < NCHUNK) stage(c + 2);
    }
    __syncthreads();    // all warps done reading smem before Gs overwrite

    // ---- epilogue: nodewise = sigmoid(gate + bg) * (t + bt) -> Gs ----
    float* Gs = sm;     // [BM][NCLASS], aliases staging buffers
    #pragma unroll
    for (int jj = 0; jj < JC; jj++) {
        const int j  = JB + jj;
        const int c0 = j * 8 + 2 * t4;
        const float bg0 = __ldg(&bg[c0]), bg1 = __ldg(&bg[c0 + 1]);
        const float bt0 = __ldg(&bt[c0]), bt1 = __ldg(&bt[c0 + 1]);
        #pragma unroll
        for (int mt = 0; mt < 2; mt++) {
            #pragma unroll
            for (int h = 0; h < 2; h++) {
                int row = wm * 32 + mt * 16 + g + h * 8;
                float gv0 = ga[mt][jj][2 * h]     + bg0;
                float gv1 = ga[mt][jj][2 * h + 1] + bg1;
                float tv0 = ta[mt][jj][2 * h]     + bt0;
                float tv1 = ta[mt][jj][2 * h + 1] + bt1;
                Gs[row * NCLASS + c0]     = sigmoidf_(gv0) * tv0;
                Gs[row * NCLASS + c0 + 1] = sigmoidf_(gv1) * tv1;
            }
        }
    }
}

// ---------------- Kernel A: HMMA gated readout + segment pooling ----------------
__global__ __launch_bounds__(TB, 1)
void nodewise_kernel(const float* __restrict__ init_states,
                     const float* __restrict__ fin_states,
                     const int*   __restrict__ gids,
                     const float* __restrict__ bg,
                     const float* __restrict__ bt)
{
    extern __shared__ float sm[];
    int* sg = (int*)((char*)sm + SMEM_MAIN);    // [BM]
    const uint32_t smem_u32 = (uint32_t)__cvta_generic_to_shared(sm);

    const int tid  = threadIdx.x;
    const int w    = tid / 32;
    const int lane = tid % 32;
    const int wm   = w & 3;             // m-group (SMSP-balanced)
    const int wn   = w >> 2;            // n-group 0..2
    const int n0   = blockIdx.x * BM;

    for (int i = tid; i < BM; i += TB) {
        int n = n0 + i;
        sg[i] = (n < N_NODES) ? gids[n] : -1;
    }

    // Compile-time j-ranges: all barriers/cp.async sequences identical across paths.
    if (wn == 0)      run_path<0, 5>(init_states, fin_states, bg, bt, sm, smem_u32, n0, tid, wm, lane);
    else if (wn == 1) run_path<5, 4>(init_states, fin_states, bg, bt, sm, smem_u32, n0, tid, wm, lane);
    else              run_path<9, 4>(init_states, fin_states, bg, bt, sm, smem_u32, n0, tid, wm, lane);

    __syncthreads();    // Gs complete (converged barrier)

    // ---- segmented pooling (nodes sorted by graph id) ----
    float* Gs = sm;
    if (tid < 2 * NCLASS) {
        const int cc  = tid % NCLASS;
        const int seg = tid / NCLASS;
        int r   = seg * 64;
        int cur = sg[r];
        float s = 0.0f;
        #pragma unroll 4
        for (int i = 0; i < 64; i++, r++) {
            int gg = sg[r];
            if (gg != cur) {
                if (cur >= 0) atomicAdd(&g_pool[cur * NCLASS + cc], s);
                s = 0.0f;
                cur = gg;
            }
            if (gg >= 0) s += Gs[r * NCLASS + cc];
        }
        if (cur >= 0) atomicAdd(&g_pool[cur * NCLASS + cc], s);
    }
}

// ---------------- Kernel B: batched per-graph BN + MLP (8 graphs/block) ----------------
#define BG 8
__global__ __launch_bounds__(256)
void graph_mlp_kernel(const float* __restrict__ aux,
                      const float* __restrict__ bn_gamma, const float* __restrict__ bn_beta,
                      const float* __restrict__ bn_mean,  const float* __restrict__ bn_var,
                      const float* __restrict__ W1, const float* __restrict__ b1,
                      const float* __restrict__ W2, const float* __restrict__ b2,
                      float* __restrict__ out)
{
    __shared__ float norm[BG][DIN];
    __shared__ float h[BG][GRAPHX];
    const int g0  = blockIdx.x * BG;
    const int tid = threadIdx.x;

    for (int i = tid; i < BG * DIN; i += 256) {
        int gi = i / DIN, d = i % DIN;
        int g  = g0 + gi;
        float ext = (d < NCLASS) ? g_pool[g * NCLASS + d]
                                 : aux[g * AUXD + (d - NCLASS)];
        norm[gi][d] = (ext - bn_mean[d]) * rsqrtf(bn_var[d] + BN_EPS) * bn_gamma[d]
                      + bn_beta[d];
    }
    __syncthreads();

    // hidden: BG x (106 -> 128)
    for (int i = tid; i < BG * GRAPHX; i += 256) {
        int gi = i >> 7, hu = i & 127;
        float acc = b1[hu];
        #pragma unroll 2
        for (int d = 0; d < DIN; d++)
            acc = fmaf(norm[gi][d], __ldg(&W1[d * GRAPHX + hu]), acc);
        h[gi][hu] = fmaxf(acc, 0.0f);
    }
    __syncthreads();

    // logits: BG x (128 -> 104)
    for (int i = tid; i < BG * NCLASS; i += 256) {
        int gi = i / NCLASS, c = i % NCLASS;
        float acc = b2[c];
        #pragma unroll 4
        for (int j = 0; j < GRAPHX; j++)
            acc = fmaf(h[gi][j], __ldg(&W2[j * NCLASS + c]), acc);
        out[(g0 + gi) * NCLASS + c] = acc;
    }
}

// ---------------- launch ----------------
extern "C" void kernel_launch(void* const* d_in, const int* in_sizes, int n_in,
                              void* d_out, int out_size)
{
    const float* init_states = (const float*)d_in[0];
    const float* fin_states  = (const float*)d_in[1];
    const float* aux         = (const float*)d_in[2];
    const int*   gids        = (const int*)  d_in[3];
    // d_in[4] = num_graphs (compile-time constant)
    const float* Wg = (const float*)d_in[5];
    const float* bg = (const float*)d_in[6];
    const float* Wt = (const float*)d_in[7];
    const float* bt = (const float*)d_in[8];
    const float* bn_gamma = (const float*)d_in[9];
    const float* bn_beta  = (const float*)d_in[10];
    const float* bn_mean  = (const float*)d_in[11];
    const float* bn_var   = (const float*)d_in[12];
    const float* W1 = (const float*)d_in[13];
    const float* b1 = (const float*)d_in[14];
    const float* W2 = (const float*)d_in[15];
    const float* b2 = (const float*)d_in[16];
    float* out = (float*)d_out;

    // Unconditional; idempotent and capture-safe.
    cudaFuncSetAttribute(nodewise_kernel,
                         cudaFuncAttributeMaxDynamicSharedMemorySize, SMEM_BYTES);

    {
        int total = NGRAPH * NCLASS;     // >= NCHUNK * B_CHUNK_U32
        prep_kernel<<<(total + 255) / 256, 256>>>(Wg, Wt);
    }
    {
        int nblk = (N_NODES + BM - 1) / BM;
        nodewise_kernel<<<nblk, TB, SMEM_BYTES>>>(init_states, fin_states, gids, bg, bt);
    }
    graph_mlp_kernel<<<NGRAPH / BG, 256>>>(aux, bn_gamma, bn_beta, bn_mean, bn_var,
                                           W1, b1, W2, b2, out);
}